// round 1
// baseline (speedup 1.0000x reference)
#include <cuda_runtime.h>
#include <cuda_bf16.h>
#include <cstdint>

// DepthToSpace, BLOCK_SIZE=2
// in : x   (B=16, C=256, H=128, W=128) fp32
// out:     (B=16, d=64,  H2=256, W2=256) fp32
//
// out[b, dd, h*2+i, w*2+k] = x[b, (i*2+k)*64 + dd, h, w]
//
// For a fixed output row (b, dd, ho): i = ho&1, h = ho>>1.
//   even wo (k=0) come from channel c0 = i*128 + dd        (contiguous in w)
//   odd  wo (k=1) come from channel c1 = i*128 + 64 + dd   (contiguous in w)
// Each thread: one float2 from each source row -> one float4 of output row.
// Both loads and the store are fully coalesced across a warp.

#define W_IN      128
#define H_IN      128
#define C_IN      256
#define D_OUT     64
#define CH_STRIDE (H_IN * W_IN)          // 16384 floats per input channel
#define ROW_F4    64                     // 256 output floats = 64 float4 per row
#define N_ROWS    (16 * D_OUT * 256)     // 262144 output rows
#define N_THREADS (N_ROWS * ROW_F4)      // 16,777,216

__global__ void __launch_bounds__(256)
d2s_kernel(const float2* __restrict__ x2, float4* __restrict__ out4) {
    unsigned tid = blockIdx.x * blockDim.x + threadIdx.x;

    unsigned j   = tid & (ROW_F4 - 1);     // float4 index within output row (0..63)
    unsigned row = tid >> 6;               // global output row (0..262143)

    unsigned ho = row & 255;               // output height index
    unsigned dd = (row >> 8) & (D_OUT - 1);
    unsigned b  = row >> 14;

    unsigned i = ho & 1;
    unsigned h = ho >> 1;

    // base channel c0 = i*128 + dd ; c1 = c0 + 64
    // float2 base index into x for (b, c0, h, 0):
    //   (((b*256 + i*128 + dd) * 128 + h) * 128) / 2   [in float2 units]
    size_t base2 = ((((size_t)b * C_IN + i * 128u + dd) * H_IN + h) * W_IN) >> 1;

    float2 av = x2[base2 + j];                               // channel c0, w = 2j, 2j+1
    float2 bv = x2[base2 + (size_t)(64 * CH_STRIDE / 2) + j]; // channel c1, same w

    // output row `row`, float4 slot j:  wo = 4j..4j+3  ->  {k=0,k=1,k=0,k=1}
    out4[(size_t)row * ROW_F4 + j] = make_float4(av.x, bv.x, av.y, bv.y);
}

extern "C" void kernel_launch(void* const* d_in, const int* in_sizes, int n_in,
                              void* d_out, int out_size) {
    const float2* x2   = (const float2*)d_in[0];
    float4*       out4 = (float4*)d_out;

    // 16,777,216 threads / 256 = 65536 blocks, exact (no tail predicate needed)
    d2s_kernel<<<N_THREADS / 256, 256>>>(x2, out4);
}

// round 2
// speedup vs baseline: 1.0609x; 1.0609x over previous
#include <cuda_runtime.h>
#include <cuda_bf16.h>
#include <cstdint>

// DepthToSpace, BLOCK_SIZE=2
// in : x   (B=16, C=256, H=128, W=128) fp32
// out:     (B=16, d=64,  H2=256, W2=256) fp32
//
// out[b, dd, h*2+i, w*2+k] = x[b, (i*2+k)*64 + dd, h, w]
//
// For a fixed output row (b, dd, ho): i = ho&1, h = ho>>1.
//   even wo (k=0) come from channel c0 = i*128 + dd        (contiguous in w)
//   odd  wo (k=1) come from channel c1 = i*128 + 64 + dd   (contiguous in w)
//
// R2: widen to 32B/thread each way. Each thread loads one float4 from the
// c0 row and one float4 from the c1 row (same w window), and writes two
// float4 of the output row. All accesses LDG.128/STG.128, fully coalesced.
// Streaming cache hints (no reuse anywhere).

#define W_IN      128
#define H_IN      128
#define C_IN      256
#define D_OUT     64
#define CH_STRIDE (H_IN * W_IN)          // 16384 floats per input channel
#define SEG_PER_ROW 32                   // 256 out floats = 32 segments of 8 (2xfloat4)
#define N_ROWS    (16 * D_OUT * 256)     // 262144 output rows
#define N_THREADS (N_ROWS * SEG_PER_ROW) // 8,388,608

__global__ void __launch_bounds__(256)
d2s_kernel(const float4* __restrict__ x4, float4* __restrict__ out4) {
    unsigned tid = blockIdx.x * blockDim.x + threadIdx.x;

    unsigned j   = tid & (SEG_PER_ROW - 1); // segment within output row (0..31)
    unsigned row = tid >> 5;                // global output row (0..262143)

    unsigned ho = row & 255;                // output height index
    unsigned dd = (row >> 8) & (D_OUT - 1);
    unsigned b  = row >> 14;

    unsigned i = ho & 1;
    unsigned h = ho >> 1;

    // float4 base index into x for (b, c0, h, 0):  c0 = i*128 + dd
    size_t base4 = ((((size_t)b * C_IN + i * 128u + dd) * H_IN + h) * W_IN) >> 2;

    float4 a = __ldcs(&x4[base4 + j]);                                // c0, w = 4j..4j+3
    float4 c = __ldcs(&x4[base4 + (size_t)(64 * CH_STRIDE / 4) + j]); // c1, same w

    // output row `row`, float4 slots 2j and 2j+1: wo = 8j..8j+7
    size_t o = (size_t)row * (SEG_PER_ROW * 2) + 2u * j;
    __stcs(&out4[o],     make_float4(a.x, c.x, a.y, c.y));
    __stcs(&out4[o + 1], make_float4(a.z, c.z, a.w, c.w));
}

extern "C" void kernel_launch(void* const* d_in, const int* in_sizes, int n_in,
                              void* d_out, int out_size) {
    const float4* x4   = (const float4*)d_in[0];
    float4*       out4 = (float4*)d_out;

    // 8,388,608 threads / 256 = 32768 blocks, exact (no tail predicate needed)
    d2s_kernel<<<N_THREADS / 256, 256>>>(x4, out4);
}